// round 8
// baseline (speedup 1.0000x reference)
#include <cuda_runtime.h>
#include <cstdint>

// ---------------------------------------------------------------------------
// GAT fused: out[M,256] = x[M,256] @ w_l^T + (sum_k w_k * neigh[M,k,256]) @ w_r^T
// A[M,512] @ B[512,256], A = [x | aggr], B rows = [w_l ; w_r].
//
// R8: TILE_M=64, THREADS=256, 2 CTAs/SM (regs<=128, 40KB static smem/CTA).
//  - Prepass kernel converts [w_l;w_r] -> tf32 into a __device__ buffer laid out
//    as the per-chunk swizzled SMEM image; main loop cp.asyncs it (no cvt/STS).
//  - A (x / weighted-neigh) register-prefetched one chunk ahead, STS'd swizzled.
//  - Double-buffered A and B, one __syncthreads per K-chunk of 16.
// ---------------------------------------------------------------------------

#define M_TOTAL  262144      // T*N
#define DIN      256
#define DOUT     256
#define KNB      5
#define TILE_M   64
#define KC       16          // K columns per chunk
#define NCH      32          // 512 / 16
#define THREADS  256

// Pre-converted, pre-swizzled B image: 32 chunks x (256 rows x 16 cols) tf32.
__device__ uint32_t g_B[NCH * DOUT * KC];   // 512 KB

__device__ __forceinline__ uint32_t f2tf32(float f) {
    uint32_t u;
    asm("cvt.rna.tf32.f32 %0, %1;" : "=r"(u) : "f"(f));
    return u;
}

__device__ __forceinline__ void mma_tf32(float* d,
                                         uint32_t a0, uint32_t a1, uint32_t a2, uint32_t a3,
                                         uint32_t b0, uint32_t b1) {
    asm volatile(
        "mma.sync.aligned.m16n8k8.row.col.f32.tf32.tf32.f32 "
        "{%0,%1,%2,%3}, {%4,%5,%6,%7}, {%8,%9}, {%0,%1,%2,%3};"
        : "+f"(d[0]), "+f"(d[1]), "+f"(d[2]), "+f"(d[3])
        : "r"(a0), "r"(a1), "r"(a2), "r"(a3), "r"(b0), "r"(b1));
}

// Swizzle within a 16-float row: float4 group g of row r stored at g ^ ((r>>1)&3).
// Conflict-free for both the STS pattern and the fragment-load pattern
// (rows differ by grp with 8-row-aligned base; bank = 16*(grp&1) + 4*(g^(grp>>1)) + qid).
__device__ __forceinline__ int swz(int row, int col) {
    return row * KC + ((((col >> 2) ^ ((row >> 1) & 3)) << 2) | (col & 3));
}

__device__ __forceinline__ void cp_async16(uint32_t dst_smem, const void* src) {
    asm volatile("cp.async.cg.shared.global [%0], [%1], 16;"
                 :: "r"(dst_smem), "l"(src));
}

// ---- prepass: [w_l ; w_r] -> tf32, chunked + swizzled image in g_B ----
__global__ void __launch_bounds__(256)
gat_prep_kernel(const float* __restrict__ wl, const float* __restrict__ wr)
{
    const int gid = blockIdx.x * 256 + threadIdx.x;   // 0 .. 32767 (one float4 each)
    const int c   = gid >> 10;          // chunk 0..31
    const int rem = gid & 1023;
    const int n   = rem >> 2;           // row 0..255
    const int g   = rem & 3;            // float4 group 0..3
    const float* wsrc = (c < 16) ? wl : wr;
    float4 v = *(const float4*)(wsrc + (size_t)n * DIN + (c & 15) * KC + g * 4);
    uint4 pv = make_uint4(f2tf32(v.x), f2tf32(v.y), f2tf32(v.z), f2tf32(v.w));
    *(uint4*)&g_B[(size_t)c * (DOUT * KC) + swz(n, g * 4)] = pv;
}

// ---- main fused kernel ----
__global__ void __launch_bounds__(THREADS, 2)
gat_mma_kernel(const float* __restrict__ x, const float* __restrict__ neigh,
               const float* __restrict__ wag, float* __restrict__ out)
{
    __shared__ uint32_t sA[2][TILE_M * KC];   // 2 x 4 KB
    __shared__ uint32_t sB[2][DOUT * KC];     // 2 x 16 KB   -> 40 KB total

    const int tid  = threadIdx.x;
    const int lane = tid & 31;
    const int wid  = tid >> 5;           // 0..7
    const int grp  = lane >> 2;          // 0..7
    const int qid  = lane & 3;           // 0..3
    const int warpM = wid >> 2;          // 0..1 (32 rows each)
    const int warpN = wid & 3;           // 0..3 (64 cols each)

    const float w0 = wag[0], w1 = wag[1], w2 = wag[2], w3 = wag[3], w4 = wag[4];
    const size_t mbase = (size_t)blockIdx.x * TILE_M;

    // A loader mapping: one float4 per thread per chunk
    const int a_r = tid >> 2;            // row 0..63
    const int a_g = tid & 3;             // float4 group 0..3
    const uint32_t a_sts_off = (uint32_t)swz(a_r, a_g * 4);

    const float* xrow = x + (mbase + (size_t)a_r) * DIN + a_g * 4;
    const float* nrow = neigh + (mbase + (size_t)a_r) * (KNB * DIN) + a_g * 4;

    float4 pre[5];   // raw prefetched A data (x: pre[0]; neigh: pre[0..4])

    float acc[2][8][4];
    #pragma unroll
    for (int i = 0; i < 2; ++i)
        #pragma unroll
        for (int j = 0; j < 8; ++j)
            #pragma unroll
            for (int q = 0; q < 4; ++q)
                acc[i][j][q] = 0.f;

    auto ldgA = [&](int d) {
        if (d < 16) {
            pre[0] = *(const float4*)(xrow + d * KC);
        } else {
            const float4* np = (const float4*)(nrow + (d - 16) * KC);
            pre[0] = np[0];
            pre[1] = np[DIN / 4];
            pre[2] = np[2 * (DIN / 4)];
            pre[3] = np[3 * (DIN / 4)];
            pre[4] = np[4 * (DIN / 4)];
        }
    };
    auto stsA = [&](int d, int buf) {
        float4 v;
        if (d < 16) {
            v = pre[0];
        } else {
            v.x = w0*pre[0].x + w1*pre[1].x + w2*pre[2].x + w3*pre[3].x + w4*pre[4].x;
            v.y = w0*pre[0].y + w1*pre[1].y + w2*pre[2].y + w3*pre[3].y + w4*pre[4].y;
            v.z = w0*pre[0].z + w1*pre[1].z + w2*pre[2].z + w3*pre[3].z + w4*pre[4].z;
            v.w = w0*pre[0].w + w1*pre[1].w + w2*pre[2].w + w3*pre[3].w + w4*pre[4].w;
        }
        *(uint4*)&sA[buf][a_sts_off] =
            make_uint4(f2tf32(v.x), f2tf32(v.y), f2tf32(v.z), f2tf32(v.w));
    };
    auto cpB = [&](int d, int buf) {
        const uint32_t* src = g_B + (size_t)d * (DOUT * KC) + tid * 4;
        uint32_t dst = (uint32_t)__cvta_generic_to_shared(&sB[buf][tid * 4]);
        #pragma unroll
        for (int i = 0; i < 4; ++i)
            cp_async16(dst + i * (THREADS * 16), src + i * (THREADS * 4));
        asm volatile("cp.async.commit_group;" ::: "memory");
    };

    // ---- prologue ----
    ldgA(0);
    stsA(0, 0);
    cpB(0, 0);
    ldgA(1);

    // ---- main loop: one sync per chunk ----
    #pragma unroll 1
    for (int c = 0; c < NCH; ++c) {
        const int cur = c & 1, nxt = cur ^ 1;

        asm volatile("cp.async.wait_group 0;" ::: "memory");
        __syncthreads();

        if (c + 1 < NCH) {
            cpB(c + 1, nxt);
            stsA(c + 1, nxt);
        }
        if (c + 2 < NCH) ldgA(c + 2);

        #pragma unroll
        for (int ks = 0; ks < 2; ++ks) {
            const int k0 = 8 * ks;
            uint32_t a[2][4];
            #pragma unroll
            for (int i = 0; i < 2; ++i) {
                const int r = warpM * 32 + i * 16 + grp;
                a[i][0] = sA[cur][swz(r,     k0 + qid)];
                a[i][1] = sA[cur][swz(r + 8, k0 + qid)];
                a[i][2] = sA[cur][swz(r,     k0 + qid + 4)];
                a[i][3] = sA[cur][swz(r + 8, k0 + qid + 4)];
            }
            #pragma unroll
            for (int j = 0; j < 8; ++j) {
                const int n = warpN * 64 + j * 8 + grp;
                const uint32_t b0 = sB[cur][swz(n, k0 + qid)];
                const uint32_t b1 = sB[cur][swz(n, k0 + qid + 4)];
                mma_tf32(acc[0][j], a[0][0], a[0][1], a[0][2], a[0][3], b0, b1);
                mma_tf32(acc[1][j], a[1][0], a[1][1], a[1][2], a[1][3], b0, b1);
            }
        }
    }

    // ---- epilogue ----
    #pragma unroll
    for (int i = 0; i < 2; ++i) {
        const size_t row = mbase + warpM * 32 + i * 16 + grp;
        #pragma unroll
        for (int j = 0; j < 8; ++j) {
            const int col = warpN * 64 + j * 8 + qid * 2;
            *(float2*)&out[row * DOUT + col] =
                make_float2(acc[i][j][0], acc[i][j][1]);
            *(float2*)&out[(row + 8) * DOUT + col] =
                make_float2(acc[i][j][2], acc[i][j][3]);
        }
    }
}

extern "C" void kernel_launch(void* const* d_in, const int* in_sizes, int n_in,
                              void* d_out, int out_size) {
    const float* x     = (const float*)d_in[0];   // [T,N,256]
    const float* neigh = (const float*)d_in[1];   // [T,N,5,256]
    const float* wag   = (const float*)d_in[2];   // [1,5]
    const float* wl    = (const float*)d_in[3];   // [256,256]
    const float* wr    = (const float*)d_in[4];   // [256,256]
    float* out         = (float*)d_out;           // [M,256]

    gat_prep_kernel<<<128, 256>>>(wl, wr);
    gat_mma_kernel<<<M_TOTAL / TILE_M, THREADS>>>(x, neigh, wag, out);
}